// round 13
// baseline (speedup 1.0000x reference)
#include <cuda_runtime.h>
#include <cuda_fp16.h>
#include <math.h>
#include <stdint.h>

// Problem dims (fixed by the dataset)
#define Bb 32
#define Ll 2048
#define Ee 1024
#define Uu 1024

// GEMM tiling (fp16 mma.sync m16n8k16), 2 CTAs/SM, 8 warps of 64x32
#define BM 128
#define BN 128
#define BKH 64                       // 64 halves per k-tile (128B data per row)
#define NKT (Ee / BKH)               // 16 k-tiles
#define ROWB 144                     // 128B data + 16B pad -> conflict-free ldmatrix
#define A_STAGE_BYTES (BM * ROWB)    // 18432
#define B_STAGE_BYTES (BN * ROWB)    // 18432
#define STAGE_BYTES (A_STAGE_BYTES + B_STAGE_BYTES)   // 36864
#define NSTAGE 3
#define SM_TILES_BYTES (NSTAGE * STAGE_BYTES)          // 110592
#define SM_BAR_OFF  (SM_TILES_BYTES)                   // 6 mbarriers (48B)
#define SM_BIAS_OFF (SM_BAR_OFF + 64)                  // 128 floats
#define SM_WC_OFF   (SM_BIAS_OFF + 512)
#define SM_V_OFF    (SM_WC_OFF + 512)
#define SM_ROW_OFF  (SM_V_OFF + 512)
#define SMEM_TOTAL  (SM_ROW_OFF + 512)                 // ~112.7KB (2/SM)

// prep_kernel block ranges (conv section removed — GEMM converts A itself)
#define PREP_TR_BLOCKS   1024
#define PREP_HW_BLOCKS   128
#define PREP_GRID (PREP_TR_BLOCKS + PREP_HW_BLOCKS)

// Scratch (no cudaMalloc allowed)
__device__ float  g_score[Bb * Ll];
__device__ float  g_hW[Bb * Uu];
__device__ __half g_encH[(size_t)Bb * Ll * Ee];   // fp16 enc (written by GEMM col-0 CTAs)
__device__ __half g_WsTH[Uu * Ee];                // transposed Ws in fp16

// ---------------------------------------------------------------------------
__device__ __forceinline__ uint32_t smem_to_u32(const void* p) {
    uint32_t a;
    asm("{ .reg .u64 t; cvta.to.shared.u64 t, %1; cvt.u32.u64 %0, t; }" : "=r"(a) : "l"(p));
    return a;
}
__device__ __forceinline__ void cp16(uint32_t dst, const void* src) {
    asm volatile("cp.async.cg.shared.global [%0], [%1], 16;" :: "r"(dst), "l"(src) : "memory");
}
__device__ __forceinline__ void sts128(uint32_t dst, uint32_t x, uint32_t y,
                                       uint32_t z, uint32_t w) {
    asm volatile("st.shared.v4.b32 [%0], {%1,%2,%3,%4};"
                 :: "r"(dst), "r"(x), "r"(y), "r"(z), "r"(w) : "memory");
}
#define MBARRIER_INIT(mbar, count) \
    asm volatile("mbarrier.init.shared.b64 [%0], %1;" \
        :: "r"((uint32_t)(mbar)), "r"((uint32_t)(count)) : "memory")
#define MBARRIER_ARRIVE(mbar) \
    asm volatile("mbarrier.arrive.shared.b64 _, [%0];" :: "r"((uint32_t)(mbar)) : "memory")
#define CPASYNC_MBAR_ARRIVE(mbar) \
    asm volatile("cp.async.mbarrier.arrive.noinc.shared.b64 [%0];" \
        :: "r"((uint32_t)(mbar)) : "memory")
#define MBARRIER_WAIT_PARITY(mbar_smem_addr, phase_parity) do { \
    uint32_t _mbar = (uint32_t)(mbar_smem_addr); \
    uint32_t _parity = (uint32_t)(phase_parity); \
    uint32_t _done; \
    asm volatile("{\n\t.reg .pred p;\n\t" \
        "mbarrier.try_wait.parity.acquire.cta.shared::cta.b64 p, [%1], %2;\n\t" \
        "selp.b32 %0, 1, 0, p;\n\t}" : "=r"(_done) : "r"(_mbar), "r"(_parity) : "memory"); \
    if (!_done) { \
        asm volatile("{\n\t.reg .pred P1;\n\t" \
            "WAIT_LOOP_%=:\n\t" \
            "mbarrier.try_wait.parity.acquire.cta.shared::cta.b64 P1, [%0], %1, 0x989680;\n\t" \
            "@P1 bra.uni WAIT_DONE_%=;\n\t" \
            "bra.uni WAIT_LOOP_%=;\n\t" \
            "WAIT_DONE_%=:\n\t}" :: "r"(_mbar), "r"(_parity) : "memory"); \
    } \
} while (0)

__device__ __forceinline__ void ldsm4(unsigned& r0, unsigned& r1, unsigned& r2,
                                      unsigned& r3, uint32_t addr) {
    asm volatile("ldmatrix.sync.aligned.m8n8.x4.shared.b16 {%0,%1,%2,%3}, [%4];"
                 : "=r"(r0), "=r"(r1), "=r"(r2), "=r"(r3) : "r"(addr));
}

__device__ __forceinline__ void mma16(float d[4], const unsigned a[4], const unsigned b[2]) {
    asm volatile(
        "mma.sync.aligned.m16n8k16.row.col.f32.f16.f16.f32 "
        "{%0,%1,%2,%3},{%4,%5,%6,%7},{%8,%9},{%0,%1,%2,%3};"
        : "+f"(d[0]), "+f"(d[1]), "+f"(d[2]), "+f"(d[3])
        : "r"(a[0]), "r"(a[1]), "r"(a[2]), "r"(a[3]), "r"(b[0]), "r"(b[1]));
}

// HW tanh approximation (MUFU.TANH, sm_75+): 1 MUFU op, |err| ~5e-4
__device__ __forceinline__ float fast_tanh(float x) {
    float y;
    asm("tanh.approx.f32 %0, %1;" : "=f"(y) : "f"(x));
    return y;
}

// ---------------------------------------------------------------------------
// prep_kernel: transpose Ws -> fp16 + hW GEMV + zero score/ctx, one launch.
//   blocks [0, 1024):      WsTH[u][e] = half(Ws[e][u])
//   blocks [1024, 1152):   g_hW = dec@Wh + biases; zero score & ctx
// ---------------------------------------------------------------------------
__global__ void __launch_bounds__(256)
prep_kernel(const float* __restrict__ Ws,
            const float* __restrict__ dec,
            const float* __restrict__ Wh,
            const float* __restrict__ Wsb,
            const float* __restrict__ Whb,
            const float* __restrict__ Wcb,
            const int* __restrict__ ucp,
            float* __restrict__ ctx) {
    __shared__ float sbuf[1056];   // union: transpose 32x33, hw dec row 1024
    const int bid = blockIdx.x;
    const int tid = threadIdx.x;

    if (bid < PREP_TR_BLOCKS) {
        // ---- Ws transpose -> fp16 ----
        const int bx = bid & 31, by = bid >> 5;
        const int tx = tid & 31, ty = tid >> 5;   // (32, 8)
#pragma unroll
        for (int j = 0; j < 4; j++)
            sbuf[(ty + j * 8) * 33 + tx] =
                Ws[(size_t)(by * 32 + ty + j * 8) * Uu + bx * 32 + tx];
        __syncthreads();
#pragma unroll
        for (int j = 0; j < 4; j++)
            g_WsTH[(size_t)(bx * 32 + ty + j * 8) * Ee + by * 32 + tx] =
                __float2half_rn(sbuf[tx * 33 + (ty + j * 8)]);
    } else {
        // ---- hW + zero score/ctx ----
        const int t = bid - PREP_TR_BLOCKS;       // 0..127
        const int uSlice = t & 3;
        const int b = t >> 2;
        const int u = uSlice * 256 + tid;

        for (int e = tid; e < Ee; e += 256) sbuf[e] = dec[b * Ee + e];
        __syncthreads();

        float acc = 0.f;
#pragma unroll 8
        for (int e = 0; e < Ee; e++) acc += sbuf[e] * Wh[(size_t)e * Uu + u];

        const int uc = *ucp;
        g_hW[b * Uu + u] = acc + Wsb[u] + Whb[u] + (uc ? Wcb[u] : 0.f);

        const int idx = t * 256 + tid;   // 0..32767
        g_score[idx * 2 + 0] = 0.f;
        g_score[idx * 2 + 1] = 0.f;
        ctx[idx] = 0.f;
    }
}

// ---------------------------------------------------------------------------
// Kernel 2: fp16 mma.sync GEMM (128x128 block, 8 warps of 64x32, 2 CTAs/SM)
// + fused tanh/V epilogue -> score. 256 threads, 3-stage mbarrier pipeline.
// A is staged from fp32 enc with in-flight fp16 conversion (LDG+CVT+STS);
// col-0 CTAs also write the converted tile to g_encH for the context kernel.
// B is staged via cp.async from the L2-resident fp16 WsTH.
// Full barrier count = 512: 256 regular arrives (A) + 256 cp.async arrives (B).
// ---------------------------------------------------------------------------
__device__ __forceinline__ void stage_a(uint32_t smBase, int buf,
                                        const float* __restrict__ aG32,
                                        __half* __restrict__ encOut,
                                        int kt, int tid, bool writeEnc) {
    const uint32_t st = smBase + buf * STAGE_BYTES;
#pragma unroll
    for (int i = 0; i < 4; i++) {
        const int c = tid + i * 256;
        const int r = c >> 3, ch = c & 7;
        const float* src = aG32 + (size_t)r * Ee + kt * BKH + ch * 8;
        const float4 v0 = *(const float4*)(src);
        const float4 v1 = *(const float4*)(src + 4);
        __half2 h0 = __floats2half2_rn(v0.x, v0.y);
        __half2 h1 = __floats2half2_rn(v0.z, v0.w);
        __half2 h2 = __floats2half2_rn(v1.x, v1.y);
        __half2 h3 = __floats2half2_rn(v1.z, v1.w);
        uint4 o;
        o.x = *(uint32_t*)&h0; o.y = *(uint32_t*)&h1;
        o.z = *(uint32_t*)&h2; o.w = *(uint32_t*)&h3;
        sts128(st + r * ROWB + ch * 16, o.x, o.y, o.z, o.w);
        if (writeEnc)
            *(uint4*)(encOut + (size_t)r * Ee + kt * BKH + ch * 8) = o;
    }
}

__device__ __forceinline__ void stage_b(uint32_t smBase, int buf,
                                        const __half* __restrict__ bG,
                                        int kt, int tid) {
    const uint32_t bO = smBase + buf * STAGE_BYTES + A_STAGE_BYTES;
#pragma unroll
    for (int i = 0; i < 4; i++) {
        const int c = tid + i * 256;
        const int r = c >> 3, ch = c & 7;
        cp16(bO + r * ROWB + ch * 16, bG + (size_t)r * Ee + kt * BKH + ch * 8);
    }
}

__global__ void __launch_bounds__(256, 2)
gemm_score_h(const float* __restrict__ enc,
             const float* __restrict__ Wc,
             const float* __restrict__ Vk,
             const float* __restrict__ cov,
             const int* __restrict__ ucp) {
    extern __shared__ char smem[];
    const uint32_t smBase = smem_to_u32(smem);
    const int tid  = threadIdx.x;
    const int wid  = tid >> 5;
    const int lane = tid & 31;
    const int g    = lane >> 2;
    const int tig  = lane & 3;
    const int wm   = wid >> 2;     // 0..1 (M)
    const int wn   = wid & 3;      // 0..3 (N)

    const int rowBase = blockIdx.y * BM;
    const int colBase = blockIdx.x * BN;
    const int b = rowBase >> 11;
    const int uc = *ucp;
    const bool writeEnc = (blockIdx.x == 0);

    const uint32_t fullB  = smBase + SM_BAR_OFF;
    const uint32_t emptyB = smBase + SM_BAR_OFF + 24;

    float* sBias = (float*)(smem + SM_BIAS_OFF);
    float* sWc   = (float*)(smem + SM_WC_OFF);
    float* sV    = (float*)(smem + SM_V_OFF);
    float* sRow  = (float*)(smem + SM_ROW_OFF);

    if (tid < 128) {
        const int u = colBase + tid;
        sBias[tid] = g_hW[b * Uu + u];
        sWc[tid]   = uc ? Wc[u] : 0.f;
        sV[tid]    = Vk[u];
        sRow[tid]  = 0.f;
    }
    if (tid < NSTAGE) {
        MBARRIER_INIT(fullB + tid * 8, 512);   // 256 regular (A) + 256 async (B)
        MBARRIER_INIT(emptyB + tid * 8, 256);
    }
    __syncthreads();   // barriers + constants visible; the ONLY block barrier

    const float*  aG32 = enc + (size_t)rowBase * Ee;
    __half*       eOut = g_encH + (size_t)rowBase * Ee;
    const __half* bG   = g_WsTH + (size_t)colBase * Ee;

    const uint32_t aLane = (uint32_t)((lane & 15) * ROWB + (lane >> 4) * 16);
    const uint32_t bLane = (uint32_t)((((lane >> 4) << 3) + (lane & 7)) * ROWB
                                      + ((lane >> 3) & 1) * 16);

    // producer cursor: starts phase 1 (first empty-waits pass immediately)
    int pStage = 0, pPhase = 1;
    // consumer cursor
    int cStage = 0, cPhase = 0;

    // prologue: stage k-tiles 0 and 1 into stages 0,1
#pragma unroll
    for (int k0 = 0; k0 < 2; k0++) {
        MBARRIER_WAIT_PARITY(emptyB + pStage * 8, pPhase);
        stage_a(smBase, pStage, aG32, eOut, k0, tid, writeEnc);
        MBARRIER_ARRIVE(fullB + pStage * 8);
        stage_b(smBase, pStage, bG, k0, tid);
        CPASYNC_MBAR_ARRIVE(fullB + pStage * 8);
        if (++pStage == NSTAGE) { pStage = 0; pPhase ^= 1; }
    }

    float acc[4][4][4];
#pragma unroll
    for (int i = 0; i < 4; i++)
#pragma unroll
        for (int j = 0; j < 4; j++)
#pragma unroll
            for (int k = 0; k < 4; k++) acc[i][j][k] = 0.f;

    for (int kt = 0; kt < NKT; kt++) {
        // produce stage for kt+2
        if (kt + 2 < NKT) {
            MBARRIER_WAIT_PARITY(emptyB + pStage * 8, pPhase);
            stage_a(smBase, pStage, aG32, eOut, kt + 2, tid, writeEnc);
            MBARRIER_ARRIVE(fullB + pStage * 8);
            stage_b(smBase, pStage, bG, kt + 2, tid);
            CPASYNC_MBAR_ARRIVE(fullB + pStage * 8);
            if (++pStage == NSTAGE) { pStage = 0; pPhase ^= 1; }
        }

        // consume stage for kt
        MBARRIER_WAIT_PARITY(fullB + cStage * 8, cPhase);

        const uint32_t sA = smBase + cStage * STAGE_BYTES;
        const uint32_t sB = sA + A_STAGE_BYTES;
        const uint32_t aBase = sA + (wm * 64) * ROWB + aLane;
        const uint32_t bBase = sB + (wn * 32) * ROWB + bLane;

        unsigned af[2][4][4];
        unsigned bf[4][2];

#pragma unroll
        for (int mi = 0; mi < 4; mi++)
            ldsm4(af[0][mi][0], af[0][mi][1], af[0][mi][2], af[0][mi][3],
                  aBase + mi * 16 * ROWB);

#pragma unroll
        for (int s = 0; s < 4; s++) {
#pragma unroll
            for (int p = 0; p < 2; p++) {
                unsigned r0, r1, r2, r3;
                ldsm4(r0, r1, r2, r3, bBase + p * 16 * ROWB + s * 32);
                bf[2 * p][0] = r0;     bf[2 * p][1] = r1;
                bf[2 * p + 1][0] = r2; bf[2 * p + 1][1] = r3;
            }
            if (s < 3) {
#pragma unroll
                for (int mi = 0; mi < 4; mi++)
                    ldsm4(af[(s + 1) & 1][mi][0], af[(s + 1) & 1][mi][1],
                          af[(s + 1) & 1][mi][2], af[(s + 1) & 1][mi][3],
                          aBase + mi * 16 * ROWB + (s + 1) * 32);
            }
#pragma unroll
            for (int mi = 0; mi < 4; mi++)
#pragma unroll
                for (int ni = 0; ni < 4; ni++)
                    mma16(acc[mi][ni], af[s & 1][mi], bf[ni]);
        }

        // all LDSMs for this stage executed -> release it
        MBARRIER_ARRIVE(emptyB + cStage * 8);
        if (++cStage == NSTAGE) { cStage = 0; cPhase ^= 1; }
    }

    // ---------------- fused epilogue ----------------
#pragma unroll
    for (int mi = 0; mi < 4; mi++) {
        const int r0 = wm * 64 + mi * 16 + g;
        const int r1 = r0 + 8;
        const float cv0 = uc ? cov[rowBase + r0] : 0.f;
        const float cv1 = uc ? cov[rowBase + r1] : 0.f;
        float s0 = 0.f, s1 = 0.f;
#pragma unroll
        for (int ni = 0; ni < 4; ni++) {
            const int c0 = wn * 32 + ni * 8 + 2 * tig;
            const int c1 = c0 + 1;
            const float b0 = sBias[c0], b1 = sBias[c1];
            const float w0 = sWc[c0],  w1 = sWc[c1];
            const float v0 = sV[c0],   v1 = sV[c1];
            s0 += fast_tanh(acc[mi][ni][0] + b0 + cv0 * w0) * v0
                + fast_tanh(acc[mi][ni][1] + b1 + cv0 * w1) * v1;
            s1 += fast_tanh(acc[mi][ni][2] + b0 + cv1 * w0) * v0
                + fast_tanh(acc[mi][ni][3] + b1 + cv1 * w1) * v1;
        }
        s0 += __shfl_xor_sync(0xFFFFFFFFu, s0, 1);
        s0 += __shfl_xor_sync(0xFFFFFFFFu, s0, 2);
        s1 += __shfl_xor_sync(0xFFFFFFFFu, s1, 1);
        s1 += __shfl_xor_sync(0xFFFFFFFFu, s1, 2);
        if (tig == 0) {
            atomicAdd(&sRow[r0], s0);
            atomicAdd(&sRow[r1], s1);
        }
    }
    __syncthreads();
    if (tid < 128) atomicAdd(&g_score[rowBase + tid], sRow[tid]);
}

// ---------------------------------------------------------------------------
// Kernel 3: masked softmax over L per batch; writes attn and coverage outputs
// ---------------------------------------------------------------------------
__global__ void softmax_kernel(const float* __restrict__ cov,
                               const float* __restrict__ Vb,
                               const int* __restrict__ mask,
                               const int* __restrict__ ucp,
                               float* __restrict__ attn,
                               float* __restrict__ covOut) {
    __shared__ float red[256];
    const int b = blockIdx.x;
    const int tid = threadIdx.x;
    const float vb = Vb[0];
    const int uc = *ucp;

    float vals[8];
    float mx = -INFINITY;
#pragma unroll
    for (int i = 0; i < 8; i++) {
        const int l = tid + i * 256;
        const float s = (g_score[b * Ll + l] + vb) * (float)mask[b * Ll + l];
        vals[i] = s;
        mx = fmaxf(mx, s);
    }
    red[tid] = mx;
    __syncthreads();
    for (int s = 128; s > 0; s >>= 1) {
        if (tid < s) red[tid] = fmaxf(red[tid], red[tid + s]);
        __syncthreads();
    }
    mx = red[0];
    __syncthreads();

    float sum = 0.f;
#pragma unroll
    for (int i = 0; i < 8; i++) {
        vals[i] = expf(vals[i] - mx);
        sum += vals[i];
    }
    red[tid] = sum;
    __syncthreads();
    for (int s = 128; s > 0; s >>= 1) {
        if (tid < s) red[tid] += red[tid + s];
        __syncthreads();
    }
    const float inv = 1.f / red[0];

#pragma unroll
    for (int i = 0; i < 8; i++) {
        const int l = tid + i * 256;
        const float w = vals[i] * inv;
        attn[b * Ll + l] = w;
        covOut[b * Ll + l] = w + (uc ? cov[b * Ll + l] : 0.f);
    }
}

// ---------------------------------------------------------------------------
// Kernel 4: context[b,e] += sum_{l in chunk} attn[b,l] * encH[b,l,e]
// grid (32, 32), 256 threads, fp16 source, atomics into pre-zeroed ctx
// ---------------------------------------------------------------------------
__global__ void __launch_bounds__(256)
context_kernel(const float* __restrict__ attn,
               float* __restrict__ ctx) {
    __shared__ float w[64];
    const int b = blockIdx.y;
    const int l0 = blockIdx.x * 64;
    if (threadIdx.x < 64) w[threadIdx.x] = attn[b * Ll + l0 + threadIdx.x];
    __syncthreads();

    const __half2* ep = (const __half2*)(g_encH + ((size_t)b * Ll + l0) * Ee)
                        + threadIdx.x * 2;
    float4 acc = make_float4(0.f, 0.f, 0.f, 0.f);
#pragma unroll 4
    for (int l = 0; l < 64; l++) {
        const float wv = w[l];
        const uint2 raw = *(const uint2*)(ep + (size_t)l * 512);
        const float2 f0 = __half22float2(*(const __half2*)&raw.x);
        const float2 f1 = __half22float2(*(const __half2*)&raw.y);
        acc.x += wv * f0.x; acc.y += wv * f0.y;
        acc.z += wv * f1.x; acc.w += wv * f1.y;
    }
    float* c = ctx + b * Ee + threadIdx.x * 4;
    atomicAdd(c + 0, acc.x);
    atomicAdd(c + 1, acc.y);
    atomicAdd(c + 2, acc.z);
    atomicAdd(c + 3, acc.w);
}

// ---------------------------------------------------------------------------
extern "C" void kernel_launch(void* const* d_in, const int* in_sizes, int n_in,
                              void* d_out, int out_size) {
    const float* dec  = (const float*)d_in[0];
    const float* enc  = (const float*)d_in[1];
    const float* cov  = (const float*)d_in[2];
    const float* Wsk  = (const float*)d_in[3];
    const float* Wsb  = (const float*)d_in[4];
    const float* Whk  = (const float*)d_in[5];
    const float* Whb  = (const float*)d_in[6];
    const float* Wck  = (const float*)d_in[7];
    const float* Wcb  = (const float*)d_in[8];
    const float* Vk   = (const float*)d_in[9];
    const float* Vb   = (const float*)d_in[10];
    const int*   mask = (const int*)d_in[11];
    const int*   ucp  = (const int*)d_in[12];

    float* out    = (float*)d_out;
    float* ctx    = out;                       // [32, 1024]
    float* attn   = out + Bb * Ee;             // [32, 2048]
    float* covOut = attn + Bb * Ll;            // [32, 2048]

    cudaFuncSetAttribute(gemm_score_h, cudaFuncAttributeMaxDynamicSharedMemorySize,
                         SMEM_TOTAL);

    prep_kernel<<<PREP_GRID, 256>>>(Wsk, dec, Whk, Wsb, Whb, Wcb, ucp, ctx);
    gemm_score_h<<<dim3(Uu / BN, (Bb * Ll) / BM), 256, SMEM_TOTAL>>>(
        enc, Wck, Vk, cov, ucp);
    softmax_kernel<<<Bb, 256>>>(cov, Vb, mask, ucp, attn, covOut);
    context_kernel<<<dim3(32, Bb), 256>>>(attn, ctx);
}

// round 14
// speedup vs baseline: 1.0695x; 1.0695x over previous
#include <cuda_runtime.h>
#include <cuda_fp16.h>
#include <math.h>
#include <stdint.h>

// Problem dims (fixed by the dataset)
#define Bb 32
#define Ll 2048
#define Ee 1024
#define Uu 1024

// GEMM tiling (fp16 mma.sync m16n8k16), 2 CTAs/SM, 8 warps of 64x32
#define BM 128
#define BN 128
#define BKH 64                       // 64 halves per k-tile (128B data per row)
#define NKT (Ee / BKH)               // 16 k-tiles
#define ROWB 144                     // 128B data + 16B pad -> conflict-free ldmatrix
#define A_STAGE_BYTES (BM * ROWB)    // 18432
#define B_STAGE_BYTES (BN * ROWB)    // 18432
#define STAGE_BYTES (A_STAGE_BYTES + B_STAGE_BYTES)   // 36864
#define NSTAGE 3
#define SM_TILES_BYTES (NSTAGE * STAGE_BYTES)          // 110592
#define SM_BAR_OFF  (SM_TILES_BYTES)                   // 6 mbarriers (48B)
#define SM_BIAS_OFF (SM_BAR_OFF + 64)                  // 128 floats
#define SM_WC_OFF   (SM_BIAS_OFF + 512)
#define SM_V_OFF    (SM_WC_OFF + 512)
#define SM_ROW_OFF  (SM_V_OFF + 512)
#define SMEM_TOTAL  (SM_ROW_OFF + 512)                 // ~112.7KB (2/SM)

// persistent GEMM: 296 CTAs (2 per SM on 148 SMs), 4096 tiles total
#define GEMM_GRID   296
#define N_TILES     4096             // 8 col-blocks x 512 row-blocks

// prep_kernel block ranges (R12 proven form)
#define PREP_CONV_BLOCKS 32768
#define PREP_TR_BLOCKS   1024
#define PREP_HW_BLOCKS   128
#define PREP_GRID (PREP_CONV_BLOCKS + PREP_TR_BLOCKS + PREP_HW_BLOCKS)

// Scratch (no cudaMalloc allowed)
__device__ float  g_score[Bb * Ll];
__device__ float  g_hW[Bb * Uu];
__device__ __half g_encH[(size_t)Bb * Ll * Ee];   // fp16 copy of enc (128MB)
__device__ __half g_WsTH[Uu * Ee];                // transposed Ws in fp16

// ---------------------------------------------------------------------------
__device__ __forceinline__ uint32_t smem_to_u32(const void* p) {
    uint32_t a;
    asm("{ .reg .u64 t; cvta.to.shared.u64 t, %1; cvt.u32.u64 %0, t; }" : "=r"(a) : "l"(p));
    return a;
}
__device__ __forceinline__ void cp16(uint32_t dst, const void* src) {
    asm volatile("cp.async.cg.shared.global [%0], [%1], 16;" :: "r"(dst), "l"(src) : "memory");
}
#define MBARRIER_INIT(mbar, count) \
    asm volatile("mbarrier.init.shared.b64 [%0], %1;" \
        :: "r"((uint32_t)(mbar)), "r"((uint32_t)(count)) : "memory")
#define MBARRIER_ARRIVE(mbar) \
    asm volatile("mbarrier.arrive.shared.b64 _, [%0];" :: "r"((uint32_t)(mbar)) : "memory")
#define CPASYNC_MBAR_ARRIVE(mbar) \
    asm volatile("cp.async.mbarrier.arrive.noinc.shared.b64 [%0];" \
        :: "r"((uint32_t)(mbar)) : "memory")
#define MBARRIER_WAIT_PARITY(mbar_smem_addr, phase_parity) do { \
    uint32_t _mbar = (uint32_t)(mbar_smem_addr); \
    uint32_t _parity = (uint32_t)(phase_parity); \
    uint32_t _done; \
    asm volatile("{\n\t.reg .pred p;\n\t" \
        "mbarrier.try_wait.parity.acquire.cta.shared::cta.b64 p, [%1], %2;\n\t" \
        "selp.b32 %0, 1, 0, p;\n\t}" : "=r"(_done) : "r"(_mbar), "r"(_parity) : "memory"); \
    if (!_done) { \
        asm volatile("{\n\t.reg .pred P1;\n\t" \
            "WAIT_LOOP_%=:\n\t" \
            "mbarrier.try_wait.parity.acquire.cta.shared::cta.b64 P1, [%0], %1, 0x989680;\n\t" \
            "@P1 bra.uni WAIT_DONE_%=;\n\t" \
            "bra.uni WAIT_LOOP_%=;\n\t" \
            "WAIT_DONE_%=:\n\t}" :: "r"(_mbar), "r"(_parity) : "memory"); \
    } \
} while (0)

__device__ __forceinline__ void ldsm4(unsigned& r0, unsigned& r1, unsigned& r2,
                                      unsigned& r3, uint32_t addr) {
    asm volatile("ldmatrix.sync.aligned.m8n8.x4.shared.b16 {%0,%1,%2,%3}, [%4];"
                 : "=r"(r0), "=r"(r1), "=r"(r2), "=r"(r3) : "r"(addr));
}

__device__ __forceinline__ void mma16(float d[4], const unsigned a[4], const unsigned b[2]) {
    asm volatile(
        "mma.sync.aligned.m16n8k16.row.col.f32.f16.f16.f32 "
        "{%0,%1,%2,%3},{%4,%5,%6,%7},{%8,%9},{%0,%1,%2,%3};"
        : "+f"(d[0]), "+f"(d[1]), "+f"(d[2]), "+f"(d[3])
        : "r"(a[0]), "r"(a[1]), "r"(a[2]), "r"(a[3]), "r"(b[0]), "r"(b[1]));
}

// HW tanh approximation (MUFU.TANH, sm_75+): 1 MUFU op, |err| ~5e-4
__device__ __forceinline__ float fast_tanh(float x) {
    float y;
    asm("tanh.approx.f32 %0, %1;" : "=f"(y) : "f"(x));
    return y;
}

// ---------------------------------------------------------------------------
// prep_kernel: fused prologue (R12 proven form).
//   blocks [0, 32768):        enc -> fp16 copy
//   blocks [32768, 33792):    WsTH[u][e] = half(Ws[e][u])
//   blocks [33792, 33920):    g_hW = dec@Wh + biases; zero score & ctx
// ---------------------------------------------------------------------------
__global__ void __launch_bounds__(256)
prep_kernel(const float* __restrict__ enc,
            const float* __restrict__ Ws,
            const float* __restrict__ dec,
            const float* __restrict__ Wh,
            const float* __restrict__ Wsb,
            const float* __restrict__ Whb,
            const float* __restrict__ Wcb,
            const int* __restrict__ ucp,
            float* __restrict__ ctx) {
    __shared__ float sbuf[1056];
    const int bid = blockIdx.x;
    const int tid = threadIdx.x;

    if (bid < PREP_CONV_BLOCKS) {
        const size_t i = ((size_t)bid * 256 + tid) * 8;
        const float4 v0 = *(const float4*)(enc + i);
        const float4 v1 = *(const float4*)(enc + i + 4);
        __half2 h0 = __floats2half2_rn(v0.x, v0.y);
        __half2 h1 = __floats2half2_rn(v0.z, v0.w);
        __half2 h2 = __floats2half2_rn(v1.x, v1.y);
        __half2 h3 = __floats2half2_rn(v1.z, v1.w);
        uint4 o;
        o.x = *(uint32_t*)&h0; o.y = *(uint32_t*)&h1;
        o.z = *(uint32_t*)&h2; o.w = *(uint32_t*)&h3;
        *(uint4*)(g_encH + i) = o;
    } else if (bid < PREP_CONV_BLOCKS + PREP_TR_BLOCKS) {
        const int t  = bid - PREP_CONV_BLOCKS;
        const int bx = t & 31, by = t >> 5;
        const int tx = tid & 31, ty = tid >> 5;
#pragma unroll
        for (int j = 0; j < 4; j++)
            sbuf[(ty + j * 8) * 33 + tx] =
                Ws[(size_t)(by * 32 + ty + j * 8) * Uu + bx * 32 + tx];
        __syncthreads();
#pragma unroll
        for (int j = 0; j < 4; j++)
            g_WsTH[(size_t)(bx * 32 + ty + j * 8) * Ee + by * 32 + tx] =
                __float2half_rn(sbuf[tx * 33 + (ty + j * 8)]);
    } else {
        const int t = bid - (PREP_CONV_BLOCKS + PREP_TR_BLOCKS);  // 0..127
        const int uSlice = t & 3;
        const int b = t >> 2;
        const int u = uSlice * 256 + tid;

        for (int e = tid; e < Ee; e += 256) sbuf[e] = dec[b * Ee + e];
        __syncthreads();

        float acc = 0.f;
#pragma unroll 8
        for (int e = 0; e < Ee; e++) acc += sbuf[e] * Wh[(size_t)e * Uu + u];

        const int uc = *ucp;
        g_hW[b * Uu + u] = acc + Wsb[u] + Whb[u] + (uc ? Wcb[u] : 0.f);

        const int idx = t * 256 + tid;
        g_score[idx * 2 + 0] = 0.f;
        g_score[idx * 2 + 1] = 0.f;
        ctx[idx] = 0.f;
    }
}

// ---------------------------------------------------------------------------
// Kernel 2: persistent fp16 mma.sync GEMM. 296 CTAs, each owns a FIXED column
// block (296 % 8 == 0) and loops over row tiles with stride 296. The 3-stage
// cp.async mbarrier pipeline streams k-tiles ACROSS tile boundaries: the next
// tile's first stages load while the current epilogue computes tanh/V.
// ---------------------------------------------------------------------------
__device__ __forceinline__ void stage_tile(uint32_t smBase, int buf,
                                           const __half* __restrict__ aG,
                                           const __half* __restrict__ bG,
                                           int kt, int tid) {
    const uint32_t st = smBase + buf * STAGE_BYTES;
#pragma unroll
    for (int i = 0; i < 4; i++) {
        const int c = tid + i * 256;
        const int r = c >> 3, ch = c & 7;
        cp16(st + r * ROWB + ch * 16, aG + (size_t)r * Ee + kt * BKH + ch * 8);
    }
    const uint32_t bO = st + A_STAGE_BYTES;
#pragma unroll
    for (int i = 0; i < 4; i++) {
        const int c = tid + i * 256;
        const int r = c >> 3, ch = c & 7;
        cp16(bO + r * ROWB + ch * 16, bG + (size_t)r * Ee + kt * BKH + ch * 8);
    }
}

__global__ void __launch_bounds__(256, 2)
gemm_score_h(const float* __restrict__ Wc,
             const float* __restrict__ Vk,
             const float* __restrict__ cov,
             const int* __restrict__ ucp) {
    extern __shared__ char smem[];
    const uint32_t smBase = smem_to_u32(smem);
    const int tid  = threadIdx.x;
    const int wid  = tid >> 5;
    const int lane = tid & 31;
    const int g    = lane >> 2;
    const int tig  = lane & 3;
    const int wm   = wid >> 2;     // 0..1 (M)
    const int wn   = wid & 3;      // 0..3 (N)

    const int t0 = blockIdx.x;
    const int colBase = (t0 & 7) * BN;             // fixed per CTA
    const int nT = (N_TILES - t0 + GEMM_GRID - 1) / GEMM_GRID;   // 13 or 14
    const int uc = *ucp;

    const uint32_t fullB  = smBase + SM_BAR_OFF;
    const uint32_t emptyB = smBase + SM_BAR_OFF + 24;

    float* sBias = (float*)(smem + SM_BIAS_OFF);
    float* sWc   = (float*)(smem + SM_WC_OFF);
    float* sV    = (float*)(smem + SM_V_OFF);
    float* sRow  = (float*)(smem + SM_ROW_OFF);

    if (tid < 128) {
        const int u = colBase + tid;
        sWc[tid]   = uc ? Wc[u] : 0.f;
        sV[tid]    = Vk[u];
        sRow[tid]  = 0.f;
        // bias for tile 0 (row-dependent)
        const int rb0 = (t0 >> 3) * BM;
        sBias[tid] = g_hW[(rb0 >> 11) * Uu + u];
    }
    if (tid < NSTAGE) {
        MBARRIER_INIT(fullB + tid * 8, 256);
        MBARRIER_INIT(emptyB + tid * 8, 256);
    }
    __syncthreads();

    const __half* bG = g_WsTH + (size_t)colBase * Ee;

    const uint32_t aLane = (uint32_t)((lane & 15) * ROWB + (lane >> 4) * 16);
    const uint32_t bLane = (uint32_t)((((lane >> 4) << 3) + (lane & 7)) * ROWB
                                      + ((lane >> 3) & 1) * 16);

    const int totalK = nT * NKT;
    int pStage = 0, pPhase = 1;   // producer (phase 1: first empty-waits pass)
    int cStage = 0, cPhase = 0;   // consumer
    int sp = 0;                   // produced stream count

    // prologue: produce first 2 stream entries
#pragma unroll
    for (int k0 = 0; k0 < 2; k0++) {
        MBARRIER_WAIT_PARITY(emptyB + pStage * 8, pPhase);
        {
            const int ti = sp >> 4, kt = sp & 15;
            const int rb = ((t0 + ti * GEMM_GRID) >> 3) * BM;
            stage_tile(smBase, pStage, g_encH + (size_t)rb * Ee, bG, kt, tid);
        }
        CPASYNC_MBAR_ARRIVE(fullB + pStage * 8);
        if (++pStage == NSTAGE) { pStage = 0; pPhase ^= 1; }
        sp++;
    }

    float acc[4][4][4];
#pragma unroll
    for (int i = 0; i < 4; i++)
#pragma unroll
        for (int j = 0; j < 4; j++)
#pragma unroll
            for (int k = 0; k < 4; k++) acc[i][j][k] = 0.f;

    for (int ti = 0; ti < nT; ti++) {
        const int rowBase = ((t0 + ti * GEMM_GRID) >> 3) * BM;

        for (int kt = 0; kt < NKT; kt++) {
            // produce 2 ahead (crosses tile boundaries)
            if (sp < totalK) {
                MBARRIER_WAIT_PARITY(emptyB + pStage * 8, pPhase);
                {
                    const int pi = sp >> 4, pk = sp & 15;
                    const int rb = ((t0 + pi * GEMM_GRID) >> 3) * BM;
                    stage_tile(smBase, pStage, g_encH + (size_t)rb * Ee, bG, pk, tid);
                }
                CPASYNC_MBAR_ARRIVE(fullB + pStage * 8);
                if (++pStage == NSTAGE) { pStage = 0; pPhase ^= 1; }
                sp++;
            }

            // consume
            MBARRIER_WAIT_PARITY(fullB + cStage * 8, cPhase);

            const uint32_t sA = smBase + cStage * STAGE_BYTES;
            const uint32_t sB = sA + A_STAGE_BYTES;
            const uint32_t aBase = sA + (wm * 64) * ROWB + aLane;
            const uint32_t bBase = sB + (wn * 32) * ROWB + bLane;

            unsigned af[2][4][4];
            unsigned bf[4][2];

#pragma unroll
            for (int mi = 0; mi < 4; mi++)
                ldsm4(af[0][mi][0], af[0][mi][1], af[0][mi][2], af[0][mi][3],
                      aBase + mi * 16 * ROWB);

#pragma unroll
            for (int s = 0; s < 4; s++) {
#pragma unroll
                for (int p = 0; p < 2; p++) {
                    unsigned r0, r1, r2, r3;
                    ldsm4(r0, r1, r2, r3, bBase + p * 16 * ROWB + s * 32);
                    bf[2 * p][0] = r0;     bf[2 * p][1] = r1;
                    bf[2 * p + 1][0] = r2; bf[2 * p + 1][1] = r3;
                }
                if (s < 3) {
#pragma unroll
                    for (int mi = 0; mi < 4; mi++)
                        ldsm4(af[(s + 1) & 1][mi][0], af[(s + 1) & 1][mi][1],
                              af[(s + 1) & 1][mi][2], af[(s + 1) & 1][mi][3],
                              aBase + mi * 16 * ROWB + (s + 1) * 32);
                }
#pragma unroll
                for (int mi = 0; mi < 4; mi++)
#pragma unroll
                    for (int ni = 0; ni < 4; ni++)
                        mma16(acc[mi][ni], af[s & 1][mi], bf[ni]);
            }

            MBARRIER_ARRIVE(emptyB + cStage * 8);
            if (++cStage == NSTAGE) { cStage = 0; cPhase ^= 1; }
        }

        // ------------- per-tile fused epilogue -------------
#pragma unroll
        for (int mi = 0; mi < 4; mi++) {
            const int r0 = wm * 64 + mi * 16 + g;
            const int r1 = r0 + 8;
            const float cv0 = uc ? cov[rowBase + r0] : 0.f;
            const float cv1 = uc ? cov[rowBase + r1] : 0.f;
            float s0 = 0.f, s1 = 0.f;
#pragma unroll
            for (int ni = 0; ni < 4; ni++) {
                const int c0 = wn * 32 + ni * 8 + 2 * tig;
                const int c1 = c0 + 1;
                const float b0 = sBias[c0], b1 = sBias[c1];
                const float w0 = sWc[c0],  w1 = sWc[c1];
                const float v0 = sV[c0],   v1 = sV[c1];
                s0 += fast_tanh(acc[mi][ni][0] + b0 + cv0 * w0) * v0
                    + fast_tanh(acc[mi][ni][1] + b1 + cv0 * w1) * v1;
                s1 += fast_tanh(acc[mi][ni][2] + b0 + cv1 * w0) * v0
                    + fast_tanh(acc[mi][ni][3] + b1 + cv1 * w1) * v1;
                // reset accumulators for next tile
                acc[mi][ni][0] = 0.f; acc[mi][ni][1] = 0.f;
                acc[mi][ni][2] = 0.f; acc[mi][ni][3] = 0.f;
            }
            s0 += __shfl_xor_sync(0xFFFFFFFFu, s0, 1);
            s0 += __shfl_xor_sync(0xFFFFFFFFu, s0, 2);
            s1 += __shfl_xor_sync(0xFFFFFFFFu, s1, 1);
            s1 += __shfl_xor_sync(0xFFFFFFFFu, s1, 2);
            if (tig == 0) {
                atomicAdd(&sRow[r0], s0);
                atomicAdd(&sRow[r1], s1);
            }
        }
        __syncthreads();
        if (tid < 128) {
            atomicAdd(&g_score[rowBase + tid], sRow[tid]);
            sRow[tid] = 0.f;
            if (ti + 1 < nT) {
                const int rbN = ((t0 + (ti + 1) * GEMM_GRID) >> 3) * BM;
                sBias[tid] = g_hW[(rbN >> 11) * Uu + colBase + tid];
            }
        }
        __syncthreads();
    }
}

// ---------------------------------------------------------------------------
// Kernel 3: masked softmax over L per batch; writes attn and coverage outputs
// ---------------------------------------------------------------------------
__global__ void softmax_kernel(const float* __restrict__ cov,
                               const float* __restrict__ Vb,
                               const int* __restrict__ mask,
                               const int* __restrict__ ucp,
                               float* __restrict__ attn,
                               float* __restrict__ covOut) {
    __shared__ float red[256];
    const int b = blockIdx.x;
    const int tid = threadIdx.x;
    const float vb = Vb[0];
    const int uc = *ucp;

    float vals[8];
    float mx = -INFINITY;
#pragma unroll
    for (int i = 0; i < 8; i++) {
        const int l = tid + i * 256;
        const float s = (g_score[b * Ll + l] + vb) * (float)mask[b * Ll + l];
        vals[i] = s;
        mx = fmaxf(mx, s);
    }
    red[tid] = mx;
    __syncthreads();
    for (int s = 128; s > 0; s >>= 1) {
        if (tid < s) red[tid] = fmaxf(red[tid], red[tid + s]);
        __syncthreads();
    }
    mx = red[0];
    __syncthreads();

    float sum = 0.f;
#pragma unroll
    for (int i = 0; i < 8; i++) {
        vals[i] = expf(vals[i] - mx);
        sum += vals[i];
    }
    red[tid] = sum;
    __syncthreads();
    for (int s = 128; s > 0; s >>= 1) {
        if (tid < s) red[tid] += red[tid + s];
        __syncthreads();
    }
    const float inv = 1.f / red[0];

#pragma unroll
    for (int i = 0; i < 8; i++) {
        const int l = tid + i * 256;
        const float w = vals[i] * inv;
        attn[b * Ll + l] = w;
        covOut[b * Ll + l] = w + (uc ? cov[b * Ll + l] : 0.f);
    }
}

// ---------------------------------------------------------------------------
// Kernel 4: context[b,e] += sum_{l in chunk} attn[b,l] * encH[b,l,e]
// grid (32, 32), 256 threads, fp16 source, atomics into pre-zeroed ctx
// ---------------------------------------------------------------------------
__global__ void __launch_bounds__(256)
context_kernel(const float* __restrict__ attn,
               float* __restrict__ ctx) {
    __shared__ float w[64];
    const int b = blockIdx.y;
    const int l0 = blockIdx.x * 64;
    if (threadIdx.x < 64) w[threadIdx.x] = attn[b * Ll + l0 + threadIdx.x];
    __syncthreads();

    const __half2* ep = (const __half2*)(g_encH + ((size_t)b * Ll + l0) * Ee)
                        + threadIdx.x * 2;
    float4 acc = make_float4(0.f, 0.f, 0.f, 0.f);
#pragma unroll 4
    for (int l = 0; l < 64; l++) {
        const float wv = w[l];
        const uint2 raw = *(const uint2*)(ep + (size_t)l * 512);
        const float2 f0 = __half22float2(*(const __half2*)&raw.x);
        const float2 f1 = __half22float2(*(const __half2*)&raw.y);
        acc.x += wv * f0.x; acc.y += wv * f0.y;
        acc.z += wv * f1.x; acc.w += wv * f1.y;
    }
    float* c = ctx + b * Ee + threadIdx.x * 4;
    atomicAdd(c + 0, acc.x);
    atomicAdd(c + 1, acc.y);
    atomicAdd(c + 2, acc.z);
    atomicAdd(c + 3, acc.w);
}

// ---------------------------------------------------------------------------
extern "C" void kernel_launch(void* const* d_in, const int* in_sizes, int n_in,
                              void* d_out, int out_size) {
    const float* dec  = (const float*)d_in[0];
    const float* enc  = (const float*)d_in[1];
    const float* cov  = (const float*)d_in[2];
    const float* Wsk  = (const float*)d_in[3];
    const float* Wsb  = (const float*)d_in[4];
    const float* Whk  = (const float*)d_in[5];
    const float* Whb  = (const float*)d_in[6];
    const float* Wck  = (const float*)d_in[7];
    const float* Wcb  = (const float*)d_in[8];
    const float* Vk   = (const float*)d_in[9];
    const float* Vb   = (const float*)d_in[10];
    const int*   mask = (const int*)d_in[11];
    const int*   ucp  = (const int*)d_in[12];

    float* out    = (float*)d_out;
    float* ctx    = out;                       // [32, 1024]
    float* attn   = out + Bb * Ee;             // [32, 2048]
    float* covOut = attn + Bb * Ll;            // [32, 2048]

    cudaFuncSetAttribute(gemm_score_h, cudaFuncAttributeMaxDynamicSharedMemorySize,
                         SMEM_TOTAL);

    prep_kernel<<<PREP_GRID, 256>>>(enc, Wsk, dec, Whk, Wsb, Whb, Wcb, ucp, ctx);
    gemm_score_h<<<GEMM_GRID, 256, SMEM_TOTAL>>>(Wck, Vk, cov, ucp);
    softmax_kernel<<<Bb, 256>>>(cov, Vb, mask, ucp, attn, covOut);
    context_kernel<<<dim3(32, Bb), 256>>>(attn, ctx);
}

// round 15
// speedup vs baseline: 1.1529x; 1.0780x over previous
#include <cuda_runtime.h>
#include <cuda_fp16.h>
#include <math.h>
#include <stdint.h>

// Problem dims (fixed by the dataset)
#define Bb 32
#define Ll 2048
#define Ee 1024
#define Uu 1024

// GEMM tiling (fp16 mma.sync m16n8k16), 2 CTAs/SM, 8 warps of 64x32
#define BM 128
#define BN 128
#define BKH 64                       // 64 halves per k-tile (128B data per row)
#define NKT (Ee / BKH)               // 16 k-tiles
#define ROWB 144                     // 128B data + 16B pad -> conflict-free ldmatrix
#define A_STAGE_BYTES (BM * ROWB)    // 18432
#define B_STAGE_BYTES (BN * ROWB)    // 18432
#define STAGE_BYTES (A_STAGE_BYTES + B_STAGE_BYTES)   // 36864
#define NSTAGE 3
#define SM_TILES_BYTES (NSTAGE * STAGE_BYTES)          // 110592
#define SM_BAR_OFF  (SM_TILES_BYTES)                   // 6 mbarriers (48B)
#define SM_BIAS_OFF (SM_BAR_OFF + 64)                  // 128 floats
#define SM_WC_OFF   (SM_BIAS_OFF + 512)
#define SM_V_OFF    (SM_WC_OFF + 512)
#define SM_ROW_OFF  (SM_V_OFF + 512)
#define SMEM_TOTAL  (SM_ROW_OFF + 512)                 // ~112.7KB (2/SM)

// prep_kernel block ranges (conv now 16 floats/thread -> 16384 blocks)
#define PREP_CONV_BLOCKS 16384
#define PREP_TR_BLOCKS   1024
#define PREP_HW_BLOCKS   128
#define PREP_GRID (PREP_CONV_BLOCKS + PREP_TR_BLOCKS + PREP_HW_BLOCKS)

// Scratch (no cudaMalloc allowed)
__device__ float  g_score[Bb * Ll];
__device__ float  g_hW[Bb * Uu];
__device__ __half g_encH[(size_t)Bb * Ll * Ee];   // fp16 copy of enc (128MB)
__device__ __half g_WsTH[Uu * Ee];                // transposed Ws in fp16

// ---------------------------------------------------------------------------
__device__ __forceinline__ uint32_t smem_to_u32(const void* p) {
    uint32_t a;
    asm("{ .reg .u64 t; cvta.to.shared.u64 t, %1; cvt.u32.u64 %0, t; }" : "=r"(a) : "l"(p));
    return a;
}
__device__ __forceinline__ void cp16(uint32_t dst, const void* src) {
    asm volatile("cp.async.cg.shared.global [%0], [%1], 16;" :: "r"(dst), "l"(src) : "memory");
}
#define MBARRIER_INIT(mbar, count) \
    asm volatile("mbarrier.init.shared.b64 [%0], %1;" \
        :: "r"((uint32_t)(mbar)), "r"((uint32_t)(count)) : "memory")
#define MBARRIER_ARRIVE(mbar) \
    asm volatile("mbarrier.arrive.shared.b64 _, [%0];" :: "r"((uint32_t)(mbar)) : "memory")
#define CPASYNC_MBAR_ARRIVE(mbar) \
    asm volatile("cp.async.mbarrier.arrive.noinc.shared.b64 [%0];" \
        :: "r"((uint32_t)(mbar)) : "memory")
#define MBARRIER_WAIT_PARITY(mbar_smem_addr, phase_parity) do { \
    uint32_t _mbar = (uint32_t)(mbar_smem_addr); \
    uint32_t _parity = (uint32_t)(phase_parity); \
    uint32_t _done; \
    asm volatile("{\n\t.reg .pred p;\n\t" \
        "mbarrier.try_wait.parity.acquire.cta.shared::cta.b64 p, [%1], %2;\n\t" \
        "selp.b32 %0, 1, 0, p;\n\t}" : "=r"(_done) : "r"(_mbar), "r"(_parity) : "memory"); \
    if (!_done) { \
        asm volatile("{\n\t.reg .pred P1;\n\t" \
            "WAIT_LOOP_%=:\n\t" \
            "mbarrier.try_wait.parity.acquire.cta.shared::cta.b64 P1, [%0], %1, 0x989680;\n\t" \
            "@P1 bra.uni WAIT_DONE_%=;\n\t" \
            "bra.uni WAIT_LOOP_%=;\n\t" \
            "WAIT_DONE_%=:\n\t}" :: "r"(_mbar), "r"(_parity) : "memory"); \
    } \
} while (0)

__device__ __forceinline__ void ldsm4(unsigned& r0, unsigned& r1, unsigned& r2,
                                      unsigned& r3, uint32_t addr) {
    asm volatile("ldmatrix.sync.aligned.m8n8.x4.shared.b16 {%0,%1,%2,%3}, [%4];"
                 : "=r"(r0), "=r"(r1), "=r"(r2), "=r"(r3) : "r"(addr));
}

__device__ __forceinline__ void mma16(float d[4], const unsigned a[4], const unsigned b[2]) {
    asm volatile(
        "mma.sync.aligned.m16n8k16.row.col.f32.f16.f16.f32 "
        "{%0,%1,%2,%3},{%4,%5,%6,%7},{%8,%9},{%0,%1,%2,%3};"
        : "+f"(d[0]), "+f"(d[1]), "+f"(d[2]), "+f"(d[3])
        : "r"(a[0]), "r"(a[1]), "r"(a[2]), "r"(a[3]), "r"(b[0]), "r"(b[1]));
}

// HW tanh approximation (MUFU.TANH, sm_75+): 1 MUFU op, |err| ~5e-4
__device__ __forceinline__ float fast_tanh(float x) {
    float y;
    asm("tanh.approx.f32 %0, %1;" : "=f"(y) : "f"(x));
    return y;
}

__device__ __forceinline__ uint4 conv8(float4 v0, float4 v1) {
    __half2 h0 = __floats2half2_rn(v0.x, v0.y);
    __half2 h1 = __floats2half2_rn(v0.z, v0.w);
    __half2 h2 = __floats2half2_rn(v1.x, v1.y);
    __half2 h3 = __floats2half2_rn(v1.z, v1.w);
    uint4 o;
    o.x = *(uint32_t*)&h0; o.y = *(uint32_t*)&h1;
    o.z = *(uint32_t*)&h2; o.w = *(uint32_t*)&h3;
    return o;
}

// ---------------------------------------------------------------------------
// prep_kernel: fused prologue (R12 structure; conv widened to 16 floats/thread
// with streaming cache hints — 4 independent LDG.128 in flight per thread).
//   blocks [0, 16384):        enc -> fp16 copy
//   blocks [16384, 17408):    WsTH[u][e] = half(Ws[e][u])
//   blocks [17408, 17536):    g_hW = dec@Wh + biases; zero score & ctx
// ---------------------------------------------------------------------------
__global__ void __launch_bounds__(256)
prep_kernel(const float* __restrict__ enc,
            const float* __restrict__ Ws,
            const float* __restrict__ dec,
            const float* __restrict__ Wh,
            const float* __restrict__ Wsb,
            const float* __restrict__ Whb,
            const float* __restrict__ Wcb,
            const int* __restrict__ ucp,
            float* __restrict__ ctx) {
    __shared__ float sbuf[1056];
    const int bid = blockIdx.x;
    const int tid = threadIdx.x;

    if (bid < PREP_CONV_BLOCKS) {
        // ---- enc -> fp16, 16 floats/thread, streaming hints ----
        const size_t i = ((size_t)bid * 256 + tid) * 16;
        const float4 v0 = __ldcs((const float4*)(enc + i));
        const float4 v1 = __ldcs((const float4*)(enc + i + 4));
        const float4 v2 = __ldcs((const float4*)(enc + i + 8));
        const float4 v3 = __ldcs((const float4*)(enc + i + 12));
        const uint4 o0 = conv8(v0, v1);
        const uint4 o1 = conv8(v2, v3);
        __stcs((uint4*)(g_encH + i), o0);
        __stcs((uint4*)(g_encH + i + 8), o1);
    } else if (bid < PREP_CONV_BLOCKS + PREP_TR_BLOCKS) {
        // ---- Ws transpose -> fp16 ----
        const int t  = bid - PREP_CONV_BLOCKS;
        const int bx = t & 31, by = t >> 5;
        const int tx = tid & 31, ty = tid >> 5;
#pragma unroll
        for (int j = 0; j < 4; j++)
            sbuf[(ty + j * 8) * 33 + tx] =
                Ws[(size_t)(by * 32 + ty + j * 8) * Uu + bx * 32 + tx];
        __syncthreads();
#pragma unroll
        for (int j = 0; j < 4; j++)
            g_WsTH[(size_t)(bx * 32 + ty + j * 8) * Ee + by * 32 + tx] =
                __float2half_rn(sbuf[tx * 33 + (ty + j * 8)]);
    } else {
        // ---- hW + zero score/ctx ----
        const int t = bid - (PREP_CONV_BLOCKS + PREP_TR_BLOCKS);  // 0..127
        const int uSlice = t & 3;
        const int b = t >> 2;
        const int u = uSlice * 256 + tid;

        for (int e = tid; e < Ee; e += 256) sbuf[e] = dec[b * Ee + e];
        __syncthreads();

        float acc = 0.f;
#pragma unroll 8
        for (int e = 0; e < Ee; e++) acc += sbuf[e] * Wh[(size_t)e * Uu + u];

        const int uc = *ucp;
        g_hW[b * Uu + u] = acc + Wsb[u] + Whb[u] + (uc ? Wcb[u] : 0.f);

        const int idx = t * 256 + tid;   // 0..32767
        g_score[idx * 2 + 0] = 0.f;
        g_score[idx * 2 + 1] = 0.f;
        ctx[idx] = 0.f;
    }
}

// ---------------------------------------------------------------------------
// Kernel 2: fp16 mma.sync GEMM (128x128 block, 8 warps of 64x32, 2 CTAs/SM)
// + fused tanh/V epilogue -> score. 256 threads, 3-stage mbarrier pipeline.
// (FROZEN: R12 form — measured best across 4 attempted restructures)
// ---------------------------------------------------------------------------
__device__ __forceinline__ void stage_tile(uint32_t smBase, int buf,
                                           const __half* __restrict__ aG,
                                           const __half* __restrict__ bG,
                                           int kt, int tid) {
    const uint32_t st = smBase + buf * STAGE_BYTES;
#pragma unroll
    for (int i = 0; i < 4; i++) {
        const int c = tid + i * 256;
        const int r = c >> 3, ch = c & 7;
        cp16(st + r * ROWB + ch * 16, aG + (size_t)r * Ee + kt * BKH + ch * 8);
    }
    const uint32_t bO = st + A_STAGE_BYTES;
#pragma unroll
    for (int i = 0; i < 4; i++) {
        const int c = tid + i * 256;
        const int r = c >> 3, ch = c & 7;
        cp16(bO + r * ROWB + ch * 16, bG + (size_t)r * Ee + kt * BKH + ch * 8);
    }
}

__global__ void __launch_bounds__(256, 2)
gemm_score_h(const float* __restrict__ Wc,
             const float* __restrict__ Vk,
             const float* __restrict__ cov,
             const int* __restrict__ ucp) {
    extern __shared__ char smem[];
    const uint32_t smBase = smem_to_u32(smem);
    const int tid  = threadIdx.x;
    const int wid  = tid >> 5;
    const int lane = tid & 31;
    const int g    = lane >> 2;
    const int tig  = lane & 3;
    const int wm   = wid >> 2;     // 0..1 (M)
    const int wn   = wid & 3;      // 0..3 (N)

    const int rowBase = blockIdx.y * BM;
    const int colBase = blockIdx.x * BN;
    const int b = rowBase >> 11;
    const int uc = *ucp;

    const uint32_t fullB  = smBase + SM_BAR_OFF;
    const uint32_t emptyB = smBase + SM_BAR_OFF + 24;

    float* sBias = (float*)(smem + SM_BIAS_OFF);
    float* sWc   = (float*)(smem + SM_WC_OFF);
    float* sV    = (float*)(smem + SM_V_OFF);
    float* sRow  = (float*)(smem + SM_ROW_OFF);

    if (tid < 128) {
        const int u = colBase + tid;
        sBias[tid] = g_hW[b * Uu + u];
        sWc[tid]   = uc ? Wc[u] : 0.f;
        sV[tid]    = Vk[u];
        sRow[tid]  = 0.f;
    }
    if (tid < NSTAGE) {
        MBARRIER_INIT(fullB + tid * 8, 256);
        MBARRIER_INIT(emptyB + tid * 8, 256);
    }
    __syncthreads();   // barriers + constants visible; the ONLY block barrier

    const __half* aG = g_encH + (size_t)rowBase * Ee;
    const __half* bG = g_WsTH + (size_t)colBase * Ee;

    const uint32_t aLane = (uint32_t)((lane & 15) * ROWB + (lane >> 4) * 16);
    const uint32_t bLane = (uint32_t)((((lane >> 4) << 3) + (lane & 7)) * ROWB
                                      + ((lane >> 3) & 1) * 16);

    // producer cursor: starts phase 1 (first empty-waits pass immediately)
    int pStage = 0, pPhase = 1;
    // consumer cursor
    int cStage = 0, cPhase = 0;

    // prologue: stage k-tiles 0 and 1 into stages 0,1
#pragma unroll
    for (int k0 = 0; k0 < 2; k0++) {
        MBARRIER_WAIT_PARITY(emptyB + pStage * 8, pPhase);
        stage_tile(smBase, pStage, aG, bG, k0, tid);
        CPASYNC_MBAR_ARRIVE(fullB + pStage * 8);
        if (++pStage == NSTAGE) { pStage = 0; pPhase ^= 1; }
    }

    float acc[4][4][4];
#pragma unroll
    for (int i = 0; i < 4; i++)
#pragma unroll
        for (int j = 0; j < 4; j++)
#pragma unroll
            for (int k = 0; k < 4; k++) acc[i][j][k] = 0.f;

    for (int kt = 0; kt < NKT; kt++) {
        // produce stage for kt+2
        if (kt + 2 < NKT) {
            MBARRIER_WAIT_PARITY(emptyB + pStage * 8, pPhase);
            stage_tile(smBase, pStage, aG, bG, kt + 2, tid);
            CPASYNC_MBAR_ARRIVE(fullB + pStage * 8);
            if (++pStage == NSTAGE) { pStage = 0; pPhase ^= 1; }
        }

        // consume stage for kt
        MBARRIER_WAIT_PARITY(fullB + cStage * 8, cPhase);

        const uint32_t sA = smBase + cStage * STAGE_BYTES;
        const uint32_t sB = sA + A_STAGE_BYTES;
        const uint32_t aBase = sA + (wm * 64) * ROWB + aLane;
        const uint32_t bBase = sB + (wn * 32) * ROWB + bLane;

        unsigned af[2][4][4];
        unsigned bf[4][2];

#pragma unroll
        for (int mi = 0; mi < 4; mi++)
            ldsm4(af[0][mi][0], af[0][mi][1], af[0][mi][2], af[0][mi][3],
                  aBase + mi * 16 * ROWB);

#pragma unroll
        for (int s = 0; s < 4; s++) {
#pragma unroll
            for (int p = 0; p < 2; p++) {
                unsigned r0, r1, r2, r3;
                ldsm4(r0, r1, r2, r3, bBase + p * 16 * ROWB + s * 32);
                bf[2 * p][0] = r0;     bf[2 * p][1] = r1;
                bf[2 * p + 1][0] = r2; bf[2 * p + 1][1] = r3;
            }
            if (s < 3) {
#pragma unroll
                for (int mi = 0; mi < 4; mi++)
                    ldsm4(af[(s + 1) & 1][mi][0], af[(s + 1) & 1][mi][1],
                          af[(s + 1) & 1][mi][2], af[(s + 1) & 1][mi][3],
                          aBase + mi * 16 * ROWB + (s + 1) * 32);
            }
#pragma unroll
            for (int mi = 0; mi < 4; mi++)
#pragma unroll
                for (int ni = 0; ni < 4; ni++)
                    mma16(acc[mi][ni], af[s & 1][mi], bf[ni]);
        }

        // all LDSMs for this stage executed -> release it
        MBARRIER_ARRIVE(emptyB + cStage * 8);
        if (++cStage == NSTAGE) { cStage = 0; cPhase ^= 1; }
    }

    // ---------------- fused epilogue ----------------
#pragma unroll
    for (int mi = 0; mi < 4; mi++) {
        const int r0 = wm * 64 + mi * 16 + g;
        const int r1 = r0 + 8;
        const float cv0 = uc ? cov[rowBase + r0] : 0.f;
        const float cv1 = uc ? cov[rowBase + r1] : 0.f;
        float s0 = 0.f, s1 = 0.f;
#pragma unroll
        for (int ni = 0; ni < 4; ni++) {
            const int c0 = wn * 32 + ni * 8 + 2 * tig;
            const int c1 = c0 + 1;
            const float b0 = sBias[c0], b1 = sBias[c1];
            const float w0 = sWc[c0],  w1 = sWc[c1];
            const float v0 = sV[c0],   v1 = sV[c1];
            s0 += fast_tanh(acc[mi][ni][0] + b0 + cv0 * w0) * v0
                + fast_tanh(acc[mi][ni][1] + b1 + cv0 * w1) * v1;
            s1 += fast_tanh(acc[mi][ni][2] + b0 + cv1 * w0) * v0
                + fast_tanh(acc[mi][ni][3] + b1 + cv1 * w1) * v1;
        }
        s0 += __shfl_xor_sync(0xFFFFFFFFu, s0, 1);
        s0 += __shfl_xor_sync(0xFFFFFFFFu, s0, 2);
        s1 += __shfl_xor_sync(0xFFFFFFFFu, s1, 1);
        s1 += __shfl_xor_sync(0xFFFFFFFFu, s1, 2);
        if (tig == 0) {
            atomicAdd(&sRow[r0], s0);
            atomicAdd(&sRow[r1], s1);
        }
    }
    __syncthreads();
    if (tid < 128) atomicAdd(&g_score[rowBase + tid], sRow[tid]);
}

// ---------------------------------------------------------------------------
// Kernel 3: masked softmax over L per batch; writes attn and coverage outputs
// ---------------------------------------------------------------------------
__global__ void softmax_kernel(const float* __restrict__ cov,
                               const float* __restrict__ Vb,
                               const int* __restrict__ mask,
                               const int* __restrict__ ucp,
                               float* __restrict__ attn,
                               float* __restrict__ covOut) {
    __shared__ float red[256];
    const int b = blockIdx.x;
    const int tid = threadIdx.x;
    const float vb = Vb[0];
    const int uc = *ucp;

    float vals[8];
    float mx = -INFINITY;
#pragma unroll
    for (int i = 0; i < 8; i++) {
        const int l = tid + i * 256;
        const float s = (g_score[b * Ll + l] + vb) * (float)mask[b * Ll + l];
        vals[i] = s;
        mx = fmaxf(mx, s);
    }
    red[tid] = mx;
    __syncthreads();
    for (int s = 128; s > 0; s >>= 1) {
        if (tid < s) red[tid] = fmaxf(red[tid], red[tid + s]);
        __syncthreads();
    }
    mx = red[0];
    __syncthreads();

    float sum = 0.f;
#pragma unroll
    for (int i = 0; i < 8; i++) {
        vals[i] = expf(vals[i] - mx);
        sum += vals[i];
    }
    red[tid] = sum;
    __syncthreads();
    for (int s = 128; s > 0; s >>= 1) {
        if (tid < s) red[tid] += red[tid + s];
        __syncthreads();
    }
    const float inv = 1.f / red[0];

#pragma unroll
    for (int i = 0; i < 8; i++) {
        const int l = tid + i * 256;
        const float w = vals[i] * inv;
        attn[b * Ll + l] = w;
        covOut[b * Ll + l] = w + (uc ? cov[b * Ll + l] : 0.f);
    }
}

// ---------------------------------------------------------------------------
// Kernel 4: context[b,e] += sum_{l in chunk} attn[b,l] * encH[b,l,e]
// grid (32, 32), 256 threads, fp16 source, atomics into pre-zeroed ctx
// ---------------------------------------------------------------------------
__global__ void __launch_bounds__(256)
context_kernel(const float* __restrict__ attn,
               float* __restrict__ ctx) {
    __shared__ float w[64];
    const int b = blockIdx.y;
    const int l0 = blockIdx.x * 64;
    if (threadIdx.x < 64) w[threadIdx.x] = attn[b * Ll + l0 + threadIdx.x];
    __syncthreads();

    const __half2* ep = (const __half2*)(g_encH + ((size_t)b * Ll + l0) * Ee)
                        + threadIdx.x * 2;
    float4 acc = make_float4(0.f, 0.f, 0.f, 0.f);
#pragma unroll 4
    for (int l = 0; l < 64; l++) {
        const float wv = w[l];
        const uint2 raw = *(const uint2*)(ep + (size_t)l * 512);
        const float2 f0 = __half22float2(*(const __half2*)&raw.x);
        const float2 f1 = __half22float2(*(const __half2*)&raw.y);
        acc.x += wv * f0.x; acc.y += wv * f0.y;
        acc.z += wv * f1.x; acc.w += wv * f1.y;
    }
    float* c = ctx + b * Ee + threadIdx.x * 4;
    atomicAdd(c + 0, acc.x);
    atomicAdd(c + 1, acc.y);
    atomicAdd(c + 2, acc.z);
    atomicAdd(c + 3, acc.w);
}

// ---------------------------------------------------------------------------
extern "C" void kernel_launch(void* const* d_in, const int* in_sizes, int n_in,
                              void* d_out, int out_size) {
    const float* dec  = (const float*)d_in[0];
    const float* enc  = (const float*)d_in[1];
    const float* cov  = (const float*)d_in[2];
    const float* Wsk  = (const float*)d_in[3];
    const float* Wsb  = (const float*)d_in[4];
    const float* Whk  = (const float*)d_in[5];
    const float* Whb  = (const float*)d_in[6];
    const float* Wck  = (const float*)d_in[7];
    const float* Wcb  = (const float*)d_in[8];
    const float* Vk   = (const float*)d_in[9];
    const float* Vb   = (const float*)d_in[10];
    const int*   mask = (const int*)d_in[11];
    const int*   ucp  = (const int*)d_in[12];

    float* out    = (float*)d_out;
    float* ctx    = out;                       // [32, 1024]
    float* attn   = out + Bb * Ee;             // [32, 2048]
    float* covOut = attn + Bb * Ll;            // [32, 2048]

    cudaFuncSetAttribute(gemm_score_h, cudaFuncAttributeMaxDynamicSharedMemorySize,
                         SMEM_TOTAL);

    prep_kernel<<<PREP_GRID, 256>>>(enc, Wsk, dec, Whk, Wsb, Whb, Wcb, ucp, ctx);
    gemm_score_h<<<dim3(Uu / BN, (Bb * Ll) / BM), 256, SMEM_TOTAL>>>(Wck, Vk, cov, ucp);
    softmax_kernel<<<Bb, 256>>>(cov, Vb, mask, ucp, attn, covOut);
    context_kernel<<<dim3(32, Bb), 256>>>(attn, ctx);
}

// round 16
// speedup vs baseline: 1.2003x; 1.0411x over previous
#include <cuda_runtime.h>
#include <cuda_fp16.h>
#include <math.h>
#include <stdint.h>

// Problem dims (fixed by the dataset)
#define Bb 32
#define Ll 2048
#define Ee 1024
#define Uu 1024

// GEMM tiling (fp16 mma.sync m16n8k16), 2 CTAs/SM, 8 warps of 64x32
#define BM 128
#define BN 128
#define BKH 64                       // 64 halves per k-tile (128B data per row)
#define NKT (Ee / BKH)               // 16 k-tiles
#define ROWB 144                     // 128B data + 16B pad -> conflict-free ldmatrix
#define A_STAGE_BYTES (BM * ROWB)    // 18432
#define B_STAGE_BYTES (BN * ROWB)    // 18432
#define STAGE_BYTES (A_STAGE_BYTES + B_STAGE_BYTES)   // 36864
#define NSTAGE 3
#define SM_TILES_BYTES (NSTAGE * STAGE_BYTES)          // 110592
#define SM_BAR_OFF  (SM_TILES_BYTES)                   // 6 mbarriers (48B)
#define SM_BIAS_OFF (SM_BAR_OFF + 64)                  // 128 floats
#define SM_WC_OFF   (SM_BIAS_OFF + 512)
#define SM_V_OFF    (SM_WC_OFF + 512)
#define SM_ROW_OFF  (SM_V_OFF + 512)
#define SMEM_TOTAL  (SM_ROW_OFF + 512)                 // ~112.7KB (2/SM)

// prep_kernel block ranges — hW FIRST (starts at t=0, overlaps conv),
// then transpose, then the conv bulk.
#define PREP_HW_BLOCKS   128
#define PREP_TR_BLOCKS   1024
#define PREP_CONV_BLOCKS 32768
#define PREP_HW_END   (PREP_HW_BLOCKS)
#define PREP_TR_END   (PREP_HW_BLOCKS + PREP_TR_BLOCKS)
#define PREP_GRID     (PREP_HW_BLOCKS + PREP_TR_BLOCKS + PREP_CONV_BLOCKS)

// Scratch (no cudaMalloc allowed)
__device__ float  g_score[Bb * Ll];
__device__ float  g_hW[Bb * Uu];
__device__ __half g_encH[(size_t)Bb * Ll * Ee];   // fp16 copy of enc (128MB)
__device__ __half g_WsTH[Uu * Ee];                // transposed Ws in fp16

// ---------------------------------------------------------------------------
__device__ __forceinline__ uint32_t smem_to_u32(const void* p) {
    uint32_t a;
    asm("{ .reg .u64 t; cvta.to.shared.u64 t, %1; cvt.u32.u64 %0, t; }" : "=r"(a) : "l"(p));
    return a;
}
__device__ __forceinline__ void cp16(uint32_t dst, const void* src) {
    asm volatile("cp.async.cg.shared.global [%0], [%1], 16;" :: "r"(dst), "l"(src) : "memory");
}
#define MBARRIER_INIT(mbar, count) \
    asm volatile("mbarrier.init.shared.b64 [%0], %1;" \
        :: "r"((uint32_t)(mbar)), "r"((uint32_t)(count)) : "memory")
#define MBARRIER_ARRIVE(mbar) \
    asm volatile("mbarrier.arrive.shared.b64 _, [%0];" :: "r"((uint32_t)(mbar)) : "memory")
#define CPASYNC_MBAR_ARRIVE(mbar) \
    asm volatile("cp.async.mbarrier.arrive.noinc.shared.b64 [%0];" \
        :: "r"((uint32_t)(mbar)) : "memory")
#define MBARRIER_WAIT_PARITY(mbar_smem_addr, phase_parity) do { \
    uint32_t _mbar = (uint32_t)(mbar_smem_addr); \
    uint32_t _parity = (uint32_t)(phase_parity); \
    uint32_t _done; \
    asm volatile("{\n\t.reg .pred p;\n\t" \
        "mbarrier.try_wait.parity.acquire.cta.shared::cta.b64 p, [%1], %2;\n\t" \
        "selp.b32 %0, 1, 0, p;\n\t}" : "=r"(_done) : "r"(_mbar), "r"(_parity) : "memory"); \
    if (!_done) { \
        asm volatile("{\n\t.reg .pred P1;\n\t" \
            "WAIT_LOOP_%=:\n\t" \
            "mbarrier.try_wait.parity.acquire.cta.shared::cta.b64 P1, [%0], %1, 0x989680;\n\t" \
            "@P1 bra.uni WAIT_DONE_%=;\n\t" \
            "bra.uni WAIT_LOOP_%=;\n\t" \
            "WAIT_DONE_%=:\n\t}" :: "r"(_mbar), "r"(_parity) : "memory"); \
    } \
} while (0)

__device__ __forceinline__ void ldsm4(unsigned& r0, unsigned& r1, unsigned& r2,
                                      unsigned& r3, uint32_t addr) {
    asm volatile("ldmatrix.sync.aligned.m8n8.x4.shared.b16 {%0,%1,%2,%3}, [%4];"
                 : "=r"(r0), "=r"(r1), "=r"(r2), "=r"(r3) : "r"(addr));
}

__device__ __forceinline__ void mma16(float d[4], const unsigned a[4], const unsigned b[2]) {
    asm volatile(
        "mma.sync.aligned.m16n8k16.row.col.f32.f16.f16.f32 "
        "{%0,%1,%2,%3},{%4,%5,%6,%7},{%8,%9},{%0,%1,%2,%3};"
        : "+f"(d[0]), "+f"(d[1]), "+f"(d[2]), "+f"(d[3])
        : "r"(a[0]), "r"(a[1]), "r"(a[2]), "r"(a[3]), "r"(b[0]), "r"(b[1]));
}

// HW tanh approximation (MUFU.TANH, sm_75+): 1 MUFU op, |err| ~5e-4
__device__ __forceinline__ float fast_tanh(float x) {
    float y;
    asm("tanh.approx.f32 %0, %1;" : "=f"(y) : "f"(x));
    return y;
}

// ---------------------------------------------------------------------------
// prep_kernel: fused prologue. Block order chosen so the low-parallelism,
// long-running hW GEMV blocks launch FIRST and overlap the conv stream:
//   blocks [0, 128):          g_hW = dec@Wh + biases; zero score & ctx
//   blocks [128, 1152):       WsTH[u][e] = half(Ws[e][u])
//   blocks [1152, 33920):     enc -> fp16 copy
// ---------------------------------------------------------------------------
__global__ void __launch_bounds__(256)
prep_kernel(const float* __restrict__ enc,
            const float* __restrict__ Ws,
            const float* __restrict__ dec,
            const float* __restrict__ Wh,
            const float* __restrict__ Wsb,
            const float* __restrict__ Whb,
            const float* __restrict__ Wcb,
            const int* __restrict__ ucp,
            float* __restrict__ ctx) {
    __shared__ float sbuf[1056];
    const int bid = blockIdx.x;
    const int tid = threadIdx.x;

    if (bid < PREP_HW_END) {
        // ---- hW + zero score/ctx (runs first, overlaps conv) ----
        const int t = bid;                        // 0..127
        const int uSlice = t & 3;
        const int b = t >> 2;
        const int u = uSlice * 256 + tid;

        for (int e = tid; e < Ee; e += 256) sbuf[e] = dec[b * Ee + e];
        __syncthreads();

        float acc = 0.f;
#pragma unroll 8
        for (int e = 0; e < Ee; e++) acc += sbuf[e] * Wh[(size_t)e * Uu + u];

        const int uc = *ucp;
        g_hW[b * Uu + u] = acc + Wsb[u] + Whb[u] + (uc ? Wcb[u] : 0.f);

        const int idx = t * 256 + tid;   // 0..32767
        g_score[idx * 2 + 0] = 0.f;
        g_score[idx * 2 + 1] = 0.f;
        ctx[idx] = 0.f;
    } else if (bid < PREP_TR_END) {
        // ---- Ws transpose -> fp16 ----
        const int t  = bid - PREP_HW_END;
        const int bx = t & 31, by = t >> 5;
        const int tx = tid & 31, ty = tid >> 5;   // (32, 8)
#pragma unroll
        for (int j = 0; j < 4; j++)
            sbuf[(ty + j * 8) * 33 + tx] =
                Ws[(size_t)(by * 32 + ty + j * 8) * Uu + bx * 32 + tx];
        __syncthreads();
#pragma unroll
        for (int j = 0; j < 4; j++)
            g_WsTH[(size_t)(bx * 32 + ty + j * 8) * Ee + by * 32 + tx] =
                __float2half_rn(sbuf[tx * 33 + (ty + j * 8)]);
    } else {
        // ---- enc -> fp16 (bulk) ----
        const int t = bid - PREP_TR_END;
        const size_t i = ((size_t)t * 256 + tid) * 8;
        const float4 v0 = *(const float4*)(enc + i);
        const float4 v1 = *(const float4*)(enc + i + 4);
        __half2 h0 = __floats2half2_rn(v0.x, v0.y);
        __half2 h1 = __floats2half2_rn(v0.z, v0.w);
        __half2 h2 = __floats2half2_rn(v1.x, v1.y);
        __half2 h3 = __floats2half2_rn(v1.z, v1.w);
        uint4 o;
        o.x = *(uint32_t*)&h0; o.y = *(uint32_t*)&h1;
        o.z = *(uint32_t*)&h2; o.w = *(uint32_t*)&h3;
        *(uint4*)(g_encH + i) = o;
    }
}

// ---------------------------------------------------------------------------
// Kernel 2: fp16 mma.sync GEMM (128x128 block, 8 warps of 64x32, 2 CTAs/SM)
// + fused tanh/V epilogue -> score. 256 threads, 3-stage mbarrier pipeline.
// (FROZEN: R12 form — measured best across 4 attempted restructures)
// ---------------------------------------------------------------------------
__device__ __forceinline__ void stage_tile(uint32_t smBase, int buf,
                                           const __half* __restrict__ aG,
                                           const __half* __restrict__ bG,
                                           int kt, int tid) {
    const uint32_t st = smBase + buf * STAGE_BYTES;
#pragma unroll
    for (int i = 0; i < 4; i++) {
        const int c = tid + i * 256;
        const int r = c >> 3, ch = c & 7;
        cp16(st + r * ROWB + ch * 16, aG + (size_t)r * Ee + kt * BKH + ch * 8);
    }
    const uint32_t bO = st + A_STAGE_BYTES;
#pragma unroll
    for (int i = 0; i < 4; i++) {
        const int c = tid + i * 256;
        const int r = c >> 3, ch = c & 7;
        cp16(bO + r * ROWB + ch * 16, bG + (size_t)r * Ee + kt * BKH + ch * 8);
    }
}

__global__ void __launch_bounds__(256, 2)
gemm_score_h(const float* __restrict__ Wc,
             const float* __restrict__ Vk,
             const float* __restrict__ cov,
             const int* __restrict__ ucp) {
    extern __shared__ char smem[];
    const uint32_t smBase = smem_to_u32(smem);
    const int tid  = threadIdx.x;
    const int wid  = tid >> 5;
    const int lane = tid & 31;
    const int g    = lane >> 2;
    const int tig  = lane & 3;
    const int wm   = wid >> 2;     // 0..1 (M)
    const int wn   = wid & 3;      // 0..3 (N)

    const int rowBase = blockIdx.y * BM;
    const int colBase = blockIdx.x * BN;
    const int b = rowBase >> 11;
    const int uc = *ucp;

    const uint32_t fullB  = smBase + SM_BAR_OFF;
    const uint32_t emptyB = smBase + SM_BAR_OFF + 24;

    float* sBias = (float*)(smem + SM_BIAS_OFF);
    float* sWc   = (float*)(smem + SM_WC_OFF);
    float* sV    = (float*)(smem + SM_V_OFF);
    float* sRow  = (float*)(smem + SM_ROW_OFF);

    if (tid < 128) {
        const int u = colBase + tid;
        sBias[tid] = g_hW[b * Uu + u];
        sWc[tid]   = uc ? Wc[u] : 0.f;
        sV[tid]    = Vk[u];
        sRow[tid]  = 0.f;
    }
    if (tid < NSTAGE) {
        MBARRIER_INIT(fullB + tid * 8, 256);
        MBARRIER_INIT(emptyB + tid * 8, 256);
    }
    __syncthreads();   // barriers + constants visible; the ONLY block barrier

    const __half* aG = g_encH + (size_t)rowBase * Ee;
    const __half* bG = g_WsTH + (size_t)colBase * Ee;

    const uint32_t aLane = (uint32_t)((lane & 15) * ROWB + (lane >> 4) * 16);
    const uint32_t bLane = (uint32_t)((((lane >> 4) << 3) + (lane & 7)) * ROWB
                                      + ((lane >> 3) & 1) * 16);

    // producer cursor: starts phase 1 (first empty-waits pass immediately)
    int pStage = 0, pPhase = 1;
    // consumer cursor
    int cStage = 0, cPhase = 0;

    // prologue: stage k-tiles 0 and 1 into stages 0,1
#pragma unroll
    for (int k0 = 0; k0 < 2; k0++) {
        MBARRIER_WAIT_PARITY(emptyB + pStage * 8, pPhase);
        stage_tile(smBase, pStage, aG, bG, k0, tid);
        CPASYNC_MBAR_ARRIVE(fullB + pStage * 8);
        if (++pStage == NSTAGE) { pStage = 0; pPhase ^= 1; }
    }

    float acc[4][4][4];
#pragma unroll
    for (int i = 0; i < 4; i++)
#pragma unroll
        for (int j = 0; j < 4; j++)
#pragma unroll
            for (int k = 0; k < 4; k++) acc[i][j][k] = 0.f;

    for (int kt = 0; kt < NKT; kt++) {
        // produce stage for kt+2
        if (kt + 2 < NKT) {
            MBARRIER_WAIT_PARITY(emptyB + pStage * 8, pPhase);
            stage_tile(smBase, pStage, aG, bG, kt + 2, tid);
            CPASYNC_MBAR_ARRIVE(fullB + pStage * 8);
            if (++pStage == NSTAGE) { pStage = 0; pPhase ^= 1; }
        }

        // consume stage for kt
        MBARRIER_WAIT_PARITY(fullB + cStage * 8, cPhase);

        const uint32_t sA = smBase + cStage * STAGE_BYTES;
        const uint32_t sB = sA + A_STAGE_BYTES;
        const uint32_t aBase = sA + (wm * 64) * ROWB + aLane;
        const uint32_t bBase = sB + (wn * 32) * ROWB + bLane;

        unsigned af[2][4][4];
        unsigned bf[4][2];

#pragma unroll
        for (int mi = 0; mi < 4; mi++)
            ldsm4(af[0][mi][0], af[0][mi][1], af[0][mi][2], af[0][mi][3],
                  aBase + mi * 16 * ROWB);

#pragma unroll
        for (int s = 0; s < 4; s++) {
#pragma unroll
            for (int p = 0; p < 2; p++) {
                unsigned r0, r1, r2, r3;
                ldsm4(r0, r1, r2, r3, bBase + p * 16 * ROWB + s * 32);
                bf[2 * p][0] = r0;     bf[2 * p][1] = r1;
                bf[2 * p + 1][0] = r2; bf[2 * p + 1][1] = r3;
            }
            if (s < 3) {
#pragma unroll
                for (int mi = 0; mi < 4; mi++)
                    ldsm4(af[(s + 1) & 1][mi][0], af[(s + 1) & 1][mi][1],
                          af[(s + 1) & 1][mi][2], af[(s + 1) & 1][mi][3],
                          aBase + mi * 16 * ROWB + (s + 1) * 32);
            }
#pragma unroll
            for (int mi = 0; mi < 4; mi++)
#pragma unroll
                for (int ni = 0; ni < 4; ni++)
                    mma16(acc[mi][ni], af[s & 1][mi], bf[ni]);
        }

        // all LDSMs for this stage executed -> release it
        MBARRIER_ARRIVE(emptyB + cStage * 8);
        if (++cStage == NSTAGE) { cStage = 0; cPhase ^= 1; }
    }

    // ---------------- fused epilogue ----------------
#pragma unroll
    for (int mi = 0; mi < 4; mi++) {
        const int r0 = wm * 64 + mi * 16 + g;
        const int r1 = r0 + 8;
        const float cv0 = uc ? cov[rowBase + r0] : 0.f;
        const float cv1 = uc ? cov[rowBase + r1] : 0.f;
        float s0 = 0.f, s1 = 0.f;
#pragma unroll
        for (int ni = 0; ni < 4; ni++) {
            const int c0 = wn * 32 + ni * 8 + 2 * tig;
            const int c1 = c0 + 1;
            const float b0 = sBias[c0], b1 = sBias[c1];
            const float w0 = sWc[c0],  w1 = sWc[c1];
            const float v0 = sV[c0],   v1 = sV[c1];
            s0 += fast_tanh(acc[mi][ni][0] + b0 + cv0 * w0) * v0
                + fast_tanh(acc[mi][ni][1] + b1 + cv0 * w1) * v1;
            s1 += fast_tanh(acc[mi][ni][2] + b0 + cv1 * w0) * v0
                + fast_tanh(acc[mi][ni][3] + b1 + cv1 * w1) * v1;
        }
        s0 += __shfl_xor_sync(0xFFFFFFFFu, s0, 1);
        s0 += __shfl_xor_sync(0xFFFFFFFFu, s0, 2);
        s1 += __shfl_xor_sync(0xFFFFFFFFu, s1, 1);
        s1 += __shfl_xor_sync(0xFFFFFFFFu, s1, 2);
        if (tig == 0) {
            atomicAdd(&sRow[r0], s0);
            atomicAdd(&sRow[r1], s1);
        }
    }
    __syncthreads();
    if (tid < 128) atomicAdd(&g_score[rowBase + tid], sRow[tid]);
}

// ---------------------------------------------------------------------------
// Kernel 3: masked softmax over L per batch; writes attn and coverage outputs
// ---------------------------------------------------------------------------
__global__ void softmax_kernel(const float* __restrict__ cov,
                               const float* __restrict__ Vb,
                               const int* __restrict__ mask,
                               const int* __restrict__ ucp,
                               float* __restrict__ attn,
                               float* __restrict__ covOut) {
    __shared__ float red[256];
    const int b = blockIdx.x;
    const int tid = threadIdx.x;
    const float vb = Vb[0];
    const int uc = *ucp;

    float vals[8];
    float mx = -INFINITY;
#pragma unroll
    for (int i = 0; i < 8; i++) {
        const int l = tid + i * 256;
        const float s = (g_score[b * Ll + l] + vb) * (float)mask[b * Ll + l];
        vals[i] = s;
        mx = fmaxf(mx, s);
    }
    red[tid] = mx;
    __syncthreads();
    for (int s = 128; s > 0; s >>= 1) {
        if (tid < s) red[tid] = fmaxf(red[tid], red[tid + s]);
        __syncthreads();
    }
    mx = red[0];
    __syncthreads();

    float sum = 0.f;
#pragma unroll
    for (int i = 0; i < 8; i++) {
        vals[i] = expf(vals[i] - mx);
        sum += vals[i];
    }
    red[tid] = sum;
    __syncthreads();
    for (int s = 128; s > 0; s >>= 1) {
        if (tid < s) red[tid] += red[tid + s];
        __syncthreads();
    }
    const float inv = 1.f / red[0];

#pragma unroll
    for (int i = 0; i < 8; i++) {
        const int l = tid + i * 256;
        const float w = vals[i] * inv;
        attn[b * Ll + l] = w;
        covOut[b * Ll + l] = w + (uc ? cov[b * Ll + l] : 0.f);
    }
}

// ---------------------------------------------------------------------------
// Kernel 4: context[b,e] += sum_{l in chunk} attn[b,l] * encH[b,l,e]
// grid (32, 32), 256 threads, fp16 source, atomics into pre-zeroed ctx
// ---------------------------------------------------------------------------
__global__ void __launch_bounds__(256)
context_kernel(const float* __restrict__ attn,
               float* __restrict__ ctx) {
    __shared__ float w[64];
    const int b = blockIdx.y;
    const int l0 = blockIdx.x * 64;
    if (threadIdx.x < 64) w[threadIdx.x] = attn[b * Ll + l0 + threadIdx.x];
    __syncthreads();

    const __half2* ep = (const __half2*)(g_encH + ((size_t)b * Ll + l0) * Ee)
                        + threadIdx.x * 2;
    float4 acc = make_float4(0.f, 0.f, 0.f, 0.f);
#pragma unroll 4
    for (int l = 0; l < 64; l++) {
        const float wv = w[l];
        const uint2 raw = *(const uint2*)(ep + (size_t)l * 512);
        const float2 f0 = __half22float2(*(const __half2*)&raw.x);
        const float2 f1 = __half22float2(*(const __half2*)&raw.y);
        acc.x += wv * f0.x; acc.y += wv * f0.y;
        acc.z += wv * f1.x; acc.w += wv * f1.y;
    }
    float* c = ctx + b * Ee + threadIdx.x * 4;
    atomicAdd(c + 0, acc.x);
    atomicAdd(c + 1, acc.y);
    atomicAdd(c + 2, acc.z);
    atomicAdd(c + 3, acc.w);
}

// ---------------------------------------------------------------------------
extern "C" void kernel_launch(void* const* d_in, const int* in_sizes, int n_in,
                              void* d_out, int out_size) {
    const float* dec  = (const float*)d_in[0];
    const float* enc  = (const float*)d_in[1];
    const float* cov  = (const float*)d_in[2];
    const float* Wsk  = (const float*)d_in[3];
    const float* Wsb  = (const float*)d_in[4];
    const float* Whk  = (const float*)d_in[5];
    const float* Whb  = (const float*)d_in[6];
    const float* Wck  = (const float*)d_in[7];
    const float* Wcb  = (const float*)d_in[8];
    const float* Vk   = (const float*)d_in[9];
    const float* Vb   = (const float*)d_in[10];
    const int*   mask = (const int*)d_in[11];
    const int*   ucp  = (const int*)d_in[12];

    float* out    = (float*)d_out;
    float* ctx    = out;                       // [32, 1024]
    float* attn   = out + Bb * Ee;             // [32, 2048]
    float* covOut = attn + Bb * Ll;            // [32, 2048]

    cudaFuncSetAttribute(gemm_score_h, cudaFuncAttributeMaxDynamicSharedMemorySize,
                         SMEM_TOTAL);

    prep_kernel<<<PREP_GRID, 256>>>(enc, Wsk, dec, Whk, Wsb, Whb, Wcb, ucp, ctx);
    gemm_score_h<<<dim3(Uu / BN, (Bb * Ll) / BM), 256, SMEM_TOTAL>>>(Wck, Vk, cov, ucp);
    softmax_kernel<<<Bb, 256>>>(cov, Vb, mask, ucp, attn, covOut);
    context_kernel<<<dim3(32, Bb), 256>>>(attn, ctx);
}